// round 13
// baseline (speedup 1.0000x reference)
#include <cuda_runtime.h>
#include <cuda_fp16.h>
#include <cstdint>
#include <math.h>

#define B_SZ 16384
#define N_SZ 1024
#define I_SZ 128
#define O_SZ 64
#define REFRACT 0.9f

#define BM 64
#define KC 128
#define NCHUNK 8
#define THREADS 256

// A stored as RAW fp32, padded rows: 64 rows x 528B (512 data + 16 pad)
#define A_ROW_BYTES 528
#define A_SLOT (64 * A_ROW_BYTES)          // 33792
#define OFF_A32 0
#define B_SLOT 16384                       // 2 pre-swizzled 64-k halves (8KB each)
#define OFF_B   (2 * A_SLOT)               // 67584
#define OFF_BIAS (OFF_B + 2 * B_SLOT)      // 100352
#define OFF_ACT  (OFF_BIAS + 256)
#define SMEM_TOTAL (OFF_ACT + 256)         // 100864

// Prepped weights, PRE-SWIZZLED per 64-k half: half c (0..15), row n, col kk ->
// byte offset c*8192 + swz(n*128 + kk*2). fp16, refractory folded, transposed.
__device__ __align__(16) unsigned short g_Wsw[O_SZ * N_SZ];
__device__ float g_bias[O_SZ];
__device__ int   g_act[O_SZ];

// ---------------- helpers ----------------
__device__ __forceinline__ uint32_t smem_u32(const void* p) {
    uint32_t a;
    asm("{ .reg .u64 t; cvta.to.shared.u64 t, %1; cvt.u32.u64 %0, t; }"
        : "=r"(a) : "l"(p));
    return a;
}
// packed f16x2: low half = f16(lo), high half = f16(hi)
__device__ __forceinline__ uint32_t pack_f16(float lo, float hi) {
    uint32_t r;
    asm("cvt.rn.f16x2.f32 %0, %1, %2;" : "=r"(r) : "f"(hi), "f"(lo));
    return r;
}
__device__ __forceinline__ uint32_t swz(uint32_t off) {
    return off ^ ((off >> 3) & 0x70);
}
__device__ __forceinline__ float2 lds_f2(uint32_t addr) {
    float2 v;
    asm volatile("ld.shared.v2.f32 {%0,%1}, [%2];"
                 : "=f"(v.x), "=f"(v.y) : "r"(addr));
    return v;
}
__device__ __forceinline__ void ldsm4(uint32_t* r, uint32_t addr) {
    asm volatile("ldmatrix.sync.aligned.m8n8.x4.shared.b16 {%0,%1,%2,%3}, [%4];"
                 : "=r"(r[0]), "=r"(r[1]), "=r"(r[2]), "=r"(r[3]) : "r"(addr));
}
__device__ __forceinline__ void mma16816(float* c, const uint32_t* a,
                                         uint32_t b0, uint32_t b1) {
    asm volatile(
        "mma.sync.aligned.m16n8k16.row.col.f32.f16.f16.f32 "
        "{%0,%1,%2,%3}, {%4,%5,%6,%7}, {%8,%9}, {%0,%1,%2,%3};"
        : "+f"(c[0]), "+f"(c[1]), "+f"(c[2]), "+f"(c[3])
        : "r"(a[0]), "r"(a[1]), "r"(a[2]), "r"(a[3]), "r"(b0), "r"(b1));
}
__device__ __forceinline__ void cp_async16(uint32_t dst, const void* src) {
    asm volatile("cp.async.cg.shared.global [%0], [%1], 16;"
                 :: "r"(dst), "l"(src) : "memory");
}
#define CP_COMMIT() asm volatile("cp.async.commit_group;" ::: "memory")
#define CP_WAIT(n)  asm volatile("cp.async.wait_group %0;" :: "n"(n) : "memory")

__device__ __forceinline__ float activate(float x, int a) {
    if (a == 0) return fmaxf(x, 0.0f);
    if (a == 1) return tanhf(x);
    if (a == 2) return 1.0f / (1.0f + expf(-x));
    return x;
}

// ---------------- prep: fold refractory, transpose, fp16, pre-swizzle ----------------
__global__ void prep_kernel(const float* __restrict__ W,
                            const float* __restrict__ bias,
                            const int* __restrict__ act) {
    int idx = blockIdx.x * blockDim.x + threadIdx.x;   // 65536
    if (idx < O_SZ * N_SZ) {
        int k = idx >> 6;        // 0..1023
        int n = idx & 63;        // output col
        float s = (k >= I_SZ && k < (N_SZ - O_SZ)) ? REFRACT : 1.0f;
        float w = W[(size_t)k * N_SZ + (N_SZ - O_SZ) + n] * s;
        const int c = k >> 6, kk = k & 63;   // 64-k half index, col within half
        const uint32_t off = swz((uint32_t)(n * 128 + kk * 2));
        *(unsigned short*)((char*)g_Wsw + (size_t)c * 8192 + off) =
            __half_as_ushort(__float2half_rn(w));
    }
    if (idx < O_SZ) {
        g_bias[idx] = bias[(N_SZ - O_SZ) + idx];
        g_act[idx]  = act[(N_SZ - O_SZ) + idx];
    }
}

// ---------------- chunk i (128 k): cp.async A raw fp32 + B pre-swizzled ----------------
__device__ __forceinline__ void cp_chunk(int i, int t, int m0, uint32_t sbse,
                                         const float* __restrict__ prev,
                                         const float* __restrict__ inp) {
    const int r = t >> 2, q = t & 3;
    // A: 64 rows x 512B; thread -> row r, quarter q (128B = 8 x 16B)
    const float* src = (i == 0)
        ? inp  + (size_t)(m0 + r) * I_SZ + q * 32
        : prev + (size_t)(m0 + r) * N_SZ + i * KC + q * 32;
    const uint32_t adst = sbse + OFF_A32 + (uint32_t)((i & 1) * A_SLOT)
                        + (uint32_t)(r * A_ROW_BYTES + q * 128);
#pragma unroll
    for (int j = 0; j < 8; j++)
        cp_async16(adst + j * 16, src + j * 4);

    // B: two pre-swizzled 8KB halves (indices 2i, 2i+1)
    const uint32_t bdst = sbse + OFF_B + (uint32_t)((i & 1) * B_SLOT);
    const char* bs = (const char*)g_Wsw + (size_t)(2 * i) * 8192;
#pragma unroll
    for (int h = 0; h < 2; h++)
#pragma unroll
        for (int p = 0; p < 2; p++)
            cp_async16(bdst + (uint32_t)(h * 8192 + (p * 256 + t) * 16),
                       bs + (size_t)h * 8192 + (size_t)(p * 256 + t) * 16);
}

// ---------------- main kernel ----------------
__global__ __launch_bounds__(THREADS, 2)
void mma_kernel(const float* __restrict__ prev,
                const float* __restrict__ inp,
                float* __restrict__ out) {
    extern __shared__ __align__(1024) char smem[];
    const uint32_t sbse = smem_u32(smem);
    const int t = threadIdx.x;
    const int lane = t & 31, wid = t >> 5;
    const int m0 = blockIdx.x * BM;

    if (t < O_SZ) {
        ((float*)(smem + OFF_BIAS))[t] = g_bias[t];
        ((int*)(smem + OFF_ACT))[t]    = g_act[t];
    }

    // warp tiling: 4 M-groups (16 rows) x 2 N-halves (32 cols)
    const int mg = wid >> 1, nh = wid & 1;
    const int lrow = lane & 7, seg = lane >> 3;
    const int browb = lrow + ((seg & 2) << 2);     // +8 for seg>=2
    const int bkb0 = (seg & 1) << 4;               // 0 or 16 bytes
    // A fragment geometry (mma.m16n8k16 row-major A):
    //   regs: (ra, c0..c0+1), (ra+8, ..), (ra, c0+8..), (ra+8, c0+8..)
    const int ra = mg * 16 + (lane >> 2);
    const uint32_t aBase = sbse + OFF_A32 +
                           (uint32_t)(ra * A_ROW_BYTES + (lane & 3) * 8);

    float acc[4][4];
#pragma unroll
    for (int j = 0; j < 4; j++)
#pragma unroll
        for (int c = 0; c < 4; c++) acc[j][c] = 0.0f;

    // prologue
    cp_chunk(0, t, m0, sbse, prev, inp);
    CP_COMMIT();
    CP_WAIT(0);
    __syncthreads();

    for (int i = 0; i < NCHUNK; i++) {
        if (i + 1 < NCHUNK) {
            cp_chunk(i + 1, t, m0, sbse, prev, inp);
            CP_COMMIT();
        }

        const uint32_t slotA = aBase + (uint32_t)((i & 1) * A_SLOT);
        const uint32_t slotB = sbse + OFF_B + (uint32_t)((i & 1) * B_SLOT);
#pragma unroll
        for (int s = 0; s < 8; s++) {
            const uint32_t aa = slotA + (uint32_t)(s * 64);
            float2 f0 = lds_f2(aa);
            float2 f1 = lds_f2(aa + 8 * A_ROW_BYTES);
            float2 f2 = lds_f2(aa + 32);
            float2 f3 = lds_f2(aa + 8 * A_ROW_BYTES + 32);
            uint32_t av[4];
            av[0] = pack_f16(f0.x, f0.y);
            av[1] = pack_f16(f1.x, f1.y);
            av[2] = pack_f16(f2.x, f2.y);
            av[3] = pack_f16(f3.x, f3.y);
            const int half = s >> 2, ss = s & 3;
#pragma unroll
            for (int jj = 0; jj < 2; jj++) {
                uint32_t bv[4];
                ldsm4(bv, slotB + (uint32_t)(half * 8192) +
                          swz((uint32_t)((nh * 32 + jj * 16 + browb) * 128 + ss * 32 + bkb0)));
                mma16816(acc[2 * jj],     av, bv[0], bv[1]);
                mma16816(acc[2 * jj + 1], av, bv[2], bv[3]);
            }
        }

        if (i + 1 < NCHUNK) {
            CP_WAIT(0);
            __syncthreads();
        }
    }

    // ---------------- epilogue ----------------
    const float* sbias = (const float*)(smem + OFF_BIAS);
    const int*   sact  = (const int*)(smem + OFF_ACT);
    const int g = lane >> 2, q = lane & 3;
    const int row0 = m0 + mg * 16 + g;
#pragma unroll
    for (int j = 0; j < 4; j++) {
        const int col = nh * 32 + (j >> 1) * 16 + (j & 1) * 8 + q * 2;
        const float b0 = sbias[col], b1 = sbias[col + 1];
        const int   i0 = sact[col],  i1 = sact[col + 1];
        float2 v0, v1;
        v0.x = activate(acc[j][0] + b0, i0);
        v0.y = activate(acc[j][1] + b1, i1);
        v1.x = activate(acc[j][2] + b0, i0);
        v1.y = activate(acc[j][3] + b1, i1);
        *(float2*)(out + (size_t)row0 * O_SZ + col)       = v0;
        *(float2*)(out + (size_t)(row0 + 8) * O_SZ + col) = v1;
    }
}

extern "C" void kernel_launch(void* const* d_in, const int* in_sizes, int n_in,
                              void* d_out, int out_size) {
    const float* prev = (const float*)d_in[0];   // [16384,1024] f32
    const float* inp  = (const float*)d_in[1];   // [16384,128]  f32
    const float* W    = (const float*)d_in[2];   // [1024,1024]  f32
    const float* bias = (const float*)d_in[3];   // [1024]       f32
    const int*   act  = (const int*)d_in[4];     // [1024]       i32
    float* out = (float*)d_out;                  // [16384,64]   f32

    cudaFuncSetAttribute(mma_kernel,
                         cudaFuncAttributeMaxDynamicSharedMemorySize, SMEM_TOTAL);

    prep_kernel<<<(O_SZ * N_SZ + 255) / 256, 256>>>(W, bias, act);
    mma_kernel<<<B_SZ / BM, THREADS, SMEM_TOTAL>>>(prev, inp, out);
}

// round 15
// speedup vs baseline: 1.0544x; 1.0544x over previous
#include <cuda_runtime.h>
#include <cuda_fp16.h>
#include <cstdint>
#include <math.h>

#define B_SZ 16384
#define N_SZ 1024
#define I_SZ 128
#define O_SZ 64
#define REFRACT 0.9f

#define BM 64
#define KC 64
#define NCHUNK 16
#define THREADS 256

// smem: A16 ring (2 x 8KB) | B ring (3 x 8KB) | bias/act
#define OFF_A16 0
#define OFF_B   16384
#define OFF_BIAS 40960
#define OFF_ACT  41216
#define SMEM_TOTAL 41472

// Prepped weights, PRE-SWIZZLED per chunk: chunk c, row n, col kk ->
// byte offset c*8192 + swz(n*128 + kk*2). fp16, refractory folded, transposed.
__device__ __align__(16) unsigned short g_Wsw[O_SZ * N_SZ];
__device__ float g_bias[O_SZ];
__device__ int   g_act[O_SZ];

// ---------------- helpers ----------------
__device__ __forceinline__ uint32_t smem_u32(const void* p) {
    uint32_t a;
    asm("{ .reg .u64 t; cvta.to.shared.u64 t, %1; cvt.u32.u64 %0, t; }"
        : "=r"(a) : "l"(p));
    return a;
}
// packed f16x2: low half = f16(lo), high half = f16(hi)
__device__ __forceinline__ uint32_t pack_f16(float lo, float hi) {
    uint32_t r;
    asm("cvt.rn.f16x2.f32 %0, %1, %2;" : "=r"(r) : "f"(hi), "f"(lo));
    return r;
}
__device__ __forceinline__ uint32_t swz(uint32_t off) {
    return off ^ ((off >> 3) & 0x70);
}
__device__ __forceinline__ void ldsm4(uint32_t* r, uint32_t addr) {
    asm volatile("ldmatrix.sync.aligned.m8n8.x4.shared.b16 {%0,%1,%2,%3}, [%4];"
                 : "=r"(r[0]), "=r"(r[1]), "=r"(r[2]), "=r"(r[3]) : "r"(addr));
}
__device__ __forceinline__ void mma16816(float* c, const uint32_t* a,
                                         uint32_t b0, uint32_t b1) {
    asm volatile(
        "mma.sync.aligned.m16n8k16.row.col.f32.f16.f16.f32 "
        "{%0,%1,%2,%3}, {%4,%5,%6,%7}, {%8,%9}, {%0,%1,%2,%3};"
        : "+f"(c[0]), "+f"(c[1]), "+f"(c[2]), "+f"(c[3])
        : "r"(a[0]), "r"(a[1]), "r"(a[2]), "r"(a[3]), "r"(b0), "r"(b1));
}
__device__ __forceinline__ void cp_async16(uint32_t dst, const void* src) {
    asm volatile("cp.async.cg.shared.global [%0], [%1], 16;"
                 :: "r"(dst), "l"(src) : "memory");
}
#define CP_COMMIT() asm volatile("cp.async.commit_group;" ::: "memory")
#define CP_WAIT(n)  asm volatile("cp.async.wait_group %0;" :: "n"(n) : "memory")

__device__ __forceinline__ float activate(float x, int a) {
    if (a == 0) return fmaxf(x, 0.0f);
    if (a == 1) return tanhf(x);
    if (a == 2) return 1.0f / (1.0f + expf(-x));
    return x;
}

// ---------------- prep: fold refractory, transpose, fp16, pre-swizzle ----------------
__global__ void prep_kernel(const float* __restrict__ W,
                            const float* __restrict__ bias,
                            const int* __restrict__ act) {
    int idx = blockIdx.x * blockDim.x + threadIdx.x;   // 65536
    if (idx < O_SZ * N_SZ) {
        int k = idx >> 6;        // 0..1023
        int n = idx & 63;        // output col
        float s = (k >= I_SZ && k < (N_SZ - O_SZ)) ? REFRACT : 1.0f;
        float w = W[(size_t)k * N_SZ + (N_SZ - O_SZ) + n] * s;
        const int c = k >> 6, kk = k & 63;
        const uint32_t off = swz((uint32_t)(n * 128 + kk * 2));
        *(unsigned short*)((char*)g_Wsw + (size_t)c * 8192 + off) =
            __half_as_ushort(__float2half_rn(w));
    }
    if (idx < O_SZ) {
        g_bias[idx] = bias[(N_SZ - O_SZ) + idx];
        g_act[idx]  = act[(N_SZ - O_SZ) + idx];
    }
}

// ---------------- A chunk: gmem -> regs (4 x LDG.128 per thread) ----------------
__device__ __forceinline__ void load_A(int i, int t, int m0,
                                       const float* __restrict__ prev,
                                       const float* __restrict__ inp,
                                       float4 (&a)[4]) {
    const int k0 = i * KC;
    const int rr = t >> 2;
    const int kf = (t & 3) * 16;
    const float* s = (k0 < I_SZ)
        ? inp  + (size_t)(m0 + rr) * I_SZ + k0 + kf
        : prev + (size_t)(m0 + rr) * N_SZ + k0 + kf;
#pragma unroll
    for (int p = 0; p < 4; p++) a[p] = ((const float4*)s)[p];
}

// ---------------- A chunk: regs -> smem (fp16 convert + swizzle) ----------------
__device__ __forceinline__ void store_A(uint32_t base, int t, const float4 (&a)[4]) {
    const int row = t >> 2;
    const int u4  = t & 3;
    uint32_t h[8];
#pragma unroll
    for (int p = 0; p < 4; p++) {
        h[2 * p]     = pack_f16(a[p].x, a[p].y);
        h[2 * p + 1] = pack_f16(a[p].z, a[p].w);
    }
    const uint32_t o0 = base + swz((uint32_t)(row * 128 + u4 * 32));
    const uint32_t o1 = base + swz((uint32_t)(row * 128 + u4 * 32 + 16));
    asm volatile("st.shared.v4.b32 [%0], {%1,%2,%3,%4};"
                 :: "r"(o0), "r"(h[0]), "r"(h[1]), "r"(h[2]), "r"(h[3]) : "memory");
    asm volatile("st.shared.v4.b32 [%0], {%1,%2,%3,%4};"
                 :: "r"(o1), "r"(h[4]), "r"(h[5]), "r"(h[6]), "r"(h[7]) : "memory");
}

// ---------------- B chunk: cp.async from pre-swizzled weights ----------------
__device__ __forceinline__ void cp_B(int i, int t, uint32_t sbse) {
    const uint32_t dst = sbse + OFF_B + (uint32_t)((i % 3) * 8192);
    const char* src = (const char*)g_Wsw + (size_t)i * 8192;
    cp_async16(dst + t * 16,        src + (size_t)t * 16);
    cp_async16(dst + 4096 + t * 16, src + 4096 + (size_t)t * 16);
}

// ---------------- main kernel ----------------
__global__ __launch_bounds__(THREADS, 2)
void mma_kernel(const float* __restrict__ prev,
                const float* __restrict__ inp,
                float* __restrict__ out) {
    extern __shared__ __align__(1024) char smem[];
    const uint32_t sbse = smem_u32(smem);
    const int t = threadIdx.x;
    const int lane = t & 31, wid = t >> 5;
    const int m0 = blockIdx.x * BM;

    if (t < O_SZ) {
        ((float*)(smem + OFF_BIAS))[t] = g_bias[t];
        ((int*)(smem + OFF_ACT))[t]    = g_act[t];
    }

    // warp tiling: 4 M-groups (16 rows) x 2 N-halves (32 cols)
    const int mg = wid >> 1, nh = wid & 1;
    const int lrow = lane & 7, seg = lane >> 3;
    const int arow = mg * 16 + lrow + ((seg & 1) << 3);
    const int akb0 = (seg & 2) << 3;
    const int browb = lrow + ((seg & 2) << 2);
    const int bkb0 = (seg & 1) << 4;

    float acc[4][4];
#pragma unroll
    for (int j = 0; j < 4; j++)
#pragma unroll
        for (int c = 0; c < 4; c++) acc[j][c] = 0.0f;

    float4 Ar[2][4];   // depth-2 register prefetch

    // prologue: A0,A1 in regs; B0,B1 in flight; A0 staged
    load_A(0, t, m0, prev, inp, Ar[0]);
    load_A(1, t, m0, prev, inp, Ar[1]);
    cp_B(0, t, sbse);
    CP_COMMIT();
    cp_B(1, t, sbse);
    CP_COMMIT();
    store_A(sbse + OFF_A16, t, Ar[0]);
    CP_WAIT(1);               // B0 arrived
    __syncthreads();

    for (int i = 0; i < NCHUNK; i++) {
        // slot (i+2)%3 free (compute(i-1) done at last sync); issue B(i+2)
        if (i + 2 < NCHUNK) {
            cp_B(i + 2, t, sbse);
            CP_COMMIT();
            // LDG chunk i+2 into the set freed when chunk i was stored
            load_A(i + 2, t, m0, prev, inp, Ar[i & 1]);
        }

        // compute chunk i
        const uint32_t stA = sbse + OFF_A16 + (uint32_t)((i & 1) * 8192);
        const uint32_t stB = sbse + OFF_B   + (uint32_t)((i % 3) * 8192);
#pragma unroll
        for (int s = 0; s < 4; s++) {
            uint32_t av[4];
            ldsm4(av, stA + swz((uint32_t)(arow * 128 + s * 32 + akb0)));
#pragma unroll
            for (int jj = 0; jj < 2; jj++) {
                uint32_t bv[4];
                ldsm4(bv, stB +
                          swz((uint32_t)((nh * 32 + jj * 16 + browb) * 128 + s * 32 + bkb0)));
                mma16816(acc[2 * jj],     av, bv[0], bv[1]);
                mma16816(acc[2 * jj + 1], av, bv[2], bv[3]);
            }
        }

        // stage chunk i+1 (loaded 2 iterations ago), after compute
        if (i + 1 < NCHUNK) {
            store_A(sbse + OFF_A16 + (uint32_t)(((i + 1) & 1) * 8192), t,
                    Ar[(i + 1) & 1]);
            // ensure B(i+1) arrived; keep B(i+2) in flight
            if (i + 2 < NCHUNK) { CP_WAIT(1); }
            else                { CP_WAIT(0); }
            __syncthreads();
        }
    }

    // ---------------- epilogue ----------------
    const float* sbias = (const float*)(smem + OFF_BIAS);
    const int*   sact  = (const int*)(smem + OFF_ACT);
    const int g = lane >> 2, q = lane & 3;
    const int row0 = m0 + mg * 16 + g;
#pragma unroll
    for (int j = 0; j < 4; j++) {
        const int col = nh * 32 + (j >> 1) * 16 + (j & 1) * 8 + q * 2;
        const float b0 = sbias[col], b1 = sbias[col + 1];
        const int   i0 = sact[col],  i1 = sact[col + 1];
        float2 v0, v1;
        v0.x = activate(acc[j][0] + b0, i0);
        v0.y = activate(acc[j][1] + b1, i1);
        v1.x = activate(acc[j][2] + b0, i0);
        v1.y = activate(acc[j][3] + b1, i1);
        *(float2*)(out + (size_t)row0 * O_SZ + col)       = v0;
        *(float2*)(out + (size_t)(row0 + 8) * O_SZ + col) = v1;
    }
}

extern "C" void kernel_launch(void* const* d_in, const int* in_sizes, int n_in,
                              void* d_out, int out_size) {
    const float* prev = (const float*)d_in[0];   // [16384,1024] f32
    const float* inp  = (const float*)d_in[1];   // [16384,128]  f32
    const float* W    = (const float*)d_in[2];   // [1024,1024]  f32
    const float* bias = (const float*)d_in[3];   // [1024]       f32
    const int*   act  = (const int*)d_in[4];     // [1024]       i32
    float* out = (float*)d_out;                  // [16384,64]   f32

    cudaFuncSetAttribute(mma_kernel,
                         cudaFuncAttributeMaxDynamicSharedMemorySize, SMEM_TOTAL);

    prep_kernel<<<(O_SZ * N_SZ + 255) / 256, 256>>>(W, bias, act);
    mma_kernel<<<B_SZ / BM, THREADS, SMEM_TOTAL>>>(prev, inp, out);
}

// round 16
// speedup vs baseline: 1.3478x; 1.2783x over previous
#include <cuda_runtime.h>
#include <cuda_fp16.h>
#include <cstdint>
#include <math.h>

#define B_SZ 16384
#define N_SZ 1024
#define I_SZ 128
#define O_SZ 64
#define REFRACT 0.9f

#define BM 64
#define KC 64
#define NCHUNK 16
#define THREADS 256

// stage: A 64x128B = 8K | B 64x128B = 8K  (two stages)
#define STAGE_BYTES 16384
#define OFF_A 0
#define OFF_B 8192
#define OFF_BIAS (2 * STAGE_BYTES)        // 32768
#define OFF_ACT  (OFF_BIAS + 256)
#define SMEM_TOTAL (OFF_ACT + 256)        // 33280

// Prepped weights, PRE-SWIZZLED per chunk: chunk c, row n, col kk ->
// byte offset c*8192 + swz(n*128 + kk*2). fp16, refractory folded, transposed.
__device__ __align__(16) unsigned short g_Wsw[O_SZ * N_SZ];
__device__ float g_bias[O_SZ];
__device__ int   g_act[O_SZ];

// ---------------- helpers ----------------
__device__ __forceinline__ uint32_t smem_u32(const void* p) {
    uint32_t a;
    asm("{ .reg .u64 t; cvta.to.shared.u64 t, %1; cvt.u32.u64 %0, t; }"
        : "=r"(a) : "l"(p));
    return a;
}
// packed f16x2: low half = f16(lo), high half = f16(hi)
__device__ __forceinline__ uint32_t pack_f16(float lo, float hi) {
    uint32_t r;
    asm("cvt.rn.f16x2.f32 %0, %1, %2;" : "=r"(r) : "f"(hi), "f"(lo));
    return r;
}
__device__ __forceinline__ uint32_t swz(uint32_t off) {
    return off ^ ((off >> 3) & 0x70);
}
__device__ __forceinline__ void ldsm4(uint32_t* r, uint32_t addr) {
    asm volatile("ldmatrix.sync.aligned.m8n8.x4.shared.b16 {%0,%1,%2,%3}, [%4];"
                 : "=r"(r[0]), "=r"(r[1]), "=r"(r[2]), "=r"(r[3]) : "r"(addr));
}
__device__ __forceinline__ void mma16816(float* c, const uint32_t* a,
                                         uint32_t b0, uint32_t b1) {
    asm volatile(
        "mma.sync.aligned.m16n8k16.row.col.f32.f16.f16.f32 "
        "{%0,%1,%2,%3}, {%4,%5,%6,%7}, {%8,%9}, {%0,%1,%2,%3};"
        : "+f"(c[0]), "+f"(c[1]), "+f"(c[2]), "+f"(c[3])
        : "r"(a[0]), "r"(a[1]), "r"(a[2]), "r"(a[3]), "r"(b0), "r"(b1));
}
__device__ __forceinline__ void cp_async16(uint32_t dst, const void* src) {
    asm volatile("cp.async.cg.shared.global [%0], [%1], 16;"
                 :: "r"(dst), "l"(src) : "memory");
}
#define CP_COMMIT() asm volatile("cp.async.commit_group;" ::: "memory")
#define CP_WAIT(n)  asm volatile("cp.async.wait_group %0;" :: "n"(n) : "memory")

__device__ __forceinline__ float activate(float x, int a) {
    if (a == 0) return fmaxf(x, 0.0f);
    if (a == 1) return tanhf(x);
    if (a == 2) return 1.0f / (1.0f + expf(-x));
    return x;
}

// ---------------- prep: fold refractory, transpose, fp16, pre-swizzle ----------------
__global__ void prep_kernel(const float* __restrict__ W,
                            const float* __restrict__ bias,
                            const int* __restrict__ act) {
    int idx = blockIdx.x * blockDim.x + threadIdx.x;   // 65536
    if (idx < O_SZ * N_SZ) {
        int k = idx >> 6;        // 0..1023
        int n = idx & 63;        // output col
        float s = (k >= I_SZ && k < (N_SZ - O_SZ)) ? REFRACT : 1.0f;
        float w = W[(size_t)k * N_SZ + (N_SZ - O_SZ) + n] * s;
        const int c = k >> 6, kk = k & 63;
        const uint32_t off = swz((uint32_t)(n * 128 + kk * 2));
        *(unsigned short*)((char*)g_Wsw + (size_t)c * 8192 + off) =
            __half_as_ushort(__float2half_rn(w));
    }
    if (idx < O_SZ) {
        g_bias[idx] = bias[(N_SZ - O_SZ) + idx];
        g_act[idx]  = act[(N_SZ - O_SZ) + idx];
    }
}

// ---------------- A chunk: gmem -> regs (4 x LDG.128 per thread) ----------------
__device__ __forceinline__ void load_A(int i, int t, int m0,
                                       const float* __restrict__ prev,
                                       const float* __restrict__ inp,
                                       float4 (&a)[4]) {
    const int k0 = i * KC;
    const int rr = t >> 2;
    const int kf = (t & 3) * 16;
    const float* s = (k0 < I_SZ)
        ? inp  + (size_t)(m0 + rr) * I_SZ + k0 + kf
        : prev + (size_t)(m0 + rr) * N_SZ + k0 + kf;
#pragma unroll
    for (int p = 0; p < 4; p++) a[p] = ((const float4*)s)[p];
}

// ---------------- A chunk: regs -> smem (fp16 convert + swizzle) ----------------
__device__ __forceinline__ void store_A(uint32_t base, int t, const float4 (&a)[4]) {
    const int row = t >> 2;
    const int u4  = t & 3;
    uint32_t h[8];
#pragma unroll
    for (int p = 0; p < 4; p++) {
        h[2 * p]     = pack_f16(a[p].x, a[p].y);
        h[2 * p + 1] = pack_f16(a[p].z, a[p].w);
    }
    const uint32_t o0 = base + OFF_A + swz((uint32_t)(row * 128 + u4 * 32));
    const uint32_t o1 = base + OFF_A + swz((uint32_t)(row * 128 + u4 * 32 + 16));
    asm volatile("st.shared.v4.b32 [%0], {%1,%2,%3,%4};"
                 :: "r"(o0), "r"(h[0]), "r"(h[1]), "r"(h[2]), "r"(h[3]) : "memory");
    asm volatile("st.shared.v4.b32 [%0], {%1,%2,%3,%4};"
                 :: "r"(o1), "r"(h[4]), "r"(h[5]), "r"(h[6]), "r"(h[7]) : "memory");
}

// ---------------- B chunk: cp.async from pre-swizzled weights into a stage ----------------
__device__ __forceinline__ void cp_B(int i, int t, uint32_t stage_base) {
    const uint32_t dst = stage_base + OFF_B;
    const char* src = (const char*)g_Wsw + (size_t)i * 8192;
    cp_async16(dst + t * 16,        src + (size_t)t * 16);
    cp_async16(dst + 4096 + t * 16, src + 4096 + (size_t)t * 16);
}

// ---------------- main kernel ----------------
__global__ __launch_bounds__(THREADS, 2)
void mma_kernel(const float* __restrict__ prev,
                const float* __restrict__ inp,
                float* __restrict__ out) {
    extern __shared__ __align__(1024) char smem[];
    const uint32_t sbse = smem_u32(smem);
    const int t = threadIdx.x;
    const int lane = t & 31, wid = t >> 5;
    const int m0 = blockIdx.x * BM;

    if (t < O_SZ) {
        ((float*)(smem + OFF_BIAS))[t] = g_bias[t];
        ((int*)(smem + OFF_ACT))[t]    = g_act[t];
    }

    // warp tiling: 4 M-groups (16 rows) x 2 N-halves (32 cols)
    const int mg = wid >> 1, nh = wid & 1;
    const int lrow = lane & 7, seg = lane >> 3;
    const int arow = mg * 16 + lrow + ((seg & 1) << 3);
    const int akb0 = (seg & 2) << 3;               // 0 or 16 bytes
    const int browb = lrow + ((seg & 2) << 2);     // +8 for seg>=2
    const int bkb0 = (seg & 1) << 4;               // 0 or 16 bytes

    float acc[4][4];
#pragma unroll
    for (int j = 0; j < 4; j++)
#pragma unroll
        for (int c = 0; c < 4; c++) acc[j][c] = 0.0f;

    float4 A[4];

    // prologue: A0 staged; B0 async to stage 0
    load_A(0, t, m0, prev, inp, A);
    cp_B(0, t, sbse);
    CP_COMMIT();
    store_A(sbse, t, A);
    CP_WAIT(0);
    __syncthreads();

    for (int i = 0; i < NCHUNK; i++) {
        // stage (i+1)&1 is free since the last sync: start B(i+1) now,
        // and A(i+1) into registers (R7 ordering)
        if (i + 1 < NCHUNK) {
            cp_B(i + 1, t, sbse + (uint32_t)(((i + 1) & 1) * STAGE_BYTES));
            CP_COMMIT();
            load_A(i + 1, t, m0, prev, inp, A);
        }

        // compute chunk i
        const uint32_t st = sbse + (uint32_t)((i & 1) * STAGE_BYTES);
#pragma unroll
        for (int s = 0; s < 4; s++) {
            uint32_t av[4];
            ldsm4(av, st + OFF_A + swz((uint32_t)(arow * 128 + s * 32 + akb0)));
#pragma unroll
            for (int jj = 0; jj < 2; jj++) {
                uint32_t bv[4];
                ldsm4(bv, st + OFF_B +
                          swz((uint32_t)((nh * 32 + jj * 16 + browb) * 128 + s * 32 + bkb0)));
                mma16816(acc[2 * jj],     av, bv[0], bv[1]);
                mma16816(acc[2 * jj + 1], av, bv[2], bv[3]);
            }
        }

        // stage A(i+1) after compute (R7 ordering), then wait B(i+1) + barrier
        if (i + 1 < NCHUNK) {
            store_A(sbse + (uint32_t)(((i + 1) & 1) * STAGE_BYTES), t, A);
            CP_WAIT(0);
            __syncthreads();
        }
    }

    // ---------------- epilogue ----------------
    const float* sbias = (const float*)(smem + OFF_BIAS);
    const int*   sact  = (const int*)(smem + OFF_ACT);
    const int g = lane >> 2, q = lane & 3;
    const int row0 = m0 + mg * 16 + g;
#pragma unroll
    for (int j = 0; j < 4; j++) {
        const int col = nh * 32 + (j >> 1) * 16 + (j & 1) * 8 + q * 2;
        const float b0 = sbias[col], b1 = sbias[col + 1];
        const int   i0 = sact[col],  i1 = sact[col + 1];
        float2 v0, v1;
        v0.x = activate(acc[j][0] + b0, i0);
        v0.y = activate(acc[j][1] + b1, i1);
        v1.x = activate(acc[j][2] + b0, i0);
        v1.y = activate(acc[j][3] + b1, i1);
        *(float2*)(out + (size_t)row0 * O_SZ + col)       = v0;
        *(float2*)(out + (size_t)(row0 + 8) * O_SZ + col) = v1;
    }
}

extern "C" void kernel_launch(void* const* d_in, const int* in_sizes, int n_in,
                              void* d_out, int out_size) {
    const float* prev = (const float*)d_in[0];   // [16384,1024] f32
    const float* inp  = (const float*)d_in[1];   // [16384,128]  f32
    const float* W    = (const float*)d_in[2];   // [1024,1024]  f32
    const float* bias = (const float*)d_in[3];   // [1024]       f32
    const int*   act  = (const int*)d_in[4];     // [1024]       i32
    float* out = (float*)d_out;                  // [16384,64]   f32

    cudaFuncSetAttribute(mma_kernel,
                         cudaFuncAttributeMaxDynamicSharedMemorySize, SMEM_TOTAL);

    prep_kernel<<<(O_SZ * N_SZ + 255) / 256, 256>>>(W, bias, act);
    mma_kernel<<<B_SZ / BM, THREADS, SMEM_TOTAL>>>(prev, inp, out);
}